// round 12
// baseline (speedup 1.0000x reference)
#include <cuda_runtime.h>
#include <cstdint>

#define N_NODES 50000
#define N_EDGES 800000
#define FDIM    64
#define NRELS   8
#define KDIM    (NRELS * FDIM)   // 512

// ---- scratch (allocation-free rule: __device__ globals) ----
// S[n, r, d] node-major accumulator = [50000, 512] fp32 (102.4 MB).
__device__ __align__(16) float    g_S[(size_t)N_NODES * KDIM];
__device__ __align__(16) int2     g_epack[N_EDGES];        // {src, dst*8+etype}
__device__ __align__(16) uint32_t g_Wtf[NRELS * FDIM * 72]; // tf32 W, padded rows
__device__ int g_deg[N_NODES];

// ---------------------------------------------------------------------------
// K0: zero the scatter accumulator S and the degree array.
// ---------------------------------------------------------------------------
__global__ void k_zero() {
    size_t i = (size_t)blockIdx.x * blockDim.x + threadIdx.x;
    if (i < (size_t)N_NODES * (KDIM / 4))
        ((float4*)g_S)[i] = make_float4(0.f, 0.f, 0.f, 0.f);
    if (i < N_NODES) g_deg[i] = 0;
}

__device__ __forceinline__ uint32_t f2tf32(float x) {
    uint32_t u;
    asm("cvt.rna.tf32.f32 %0, %1;" : "=r"(u) : "f"(x));
    return u;
}

// ---------------------------------------------------------------------------
// K0b: pre-convert W to tf32 into padded [8][64][72] layout (cp.async source).
// ---------------------------------------------------------------------------
__global__ void k_cvtW(const float* __restrict__ W) {
    int i = blockIdx.x * blockDim.x + threadIdx.x;   // over 8*64*64
    if (i >= NRELS * FDIM * FDIM) return;
    int r = i >> 12, row = (i >> 6) & 63, col = i & 63;
    g_Wtf[(r * FDIM + row) * 72 + col] = f2tf32(W[i]);
}

// ---------------------------------------------------------------------------
// K1: fused degree histogram + edge-index packing.
// ---------------------------------------------------------------------------
__global__ void k_pack_deg(const int* __restrict__ src, const int* __restrict__ dst,
                           const int* __restrict__ et) {
    int e = blockIdx.x * blockDim.x + threadIdx.x;
    if (e >= N_EDGES) return;
    int d = dst[e];
    g_epack[e] = make_int2(src[e], d * NRELS + et[e]);
    atomicAdd(&g_deg[d], 1);
}

// ---------------------------------------------------------------------------
// K2: edge scatter of RAW features. 16 lanes per edge, one float4 each.
// REDG-issue bound (structural floor ~50us).
// ---------------------------------------------------------------------------
__global__ void k_scatter(const float4* __restrict__ feat4) {
    int t = blockIdx.x * blockDim.x + threadIdx.x;
    int e = t >> 4;
    int l = t & 15;
    if (e >= N_EDGES) return;
    int2 idx = __ldg(&g_epack[e]);
    float4 v = __ldg(&feat4[(size_t)idx.x * (FDIM / 4) + l]);
    float* o = g_S + (size_t)idx.y * FDIM + l * 4;
    asm volatile("red.global.add.v4.f32 [%0], {%1,%2,%3,%4};"
                 :: "l"(o), "f"(v.x), "f"(v.y), "f"(v.z), "f"(v.w) : "memory");
}

// ---------------------------------------------------------------------------
// K3: fused GEMM + epilogue with cp.async DOUBLE-BUFFERED pipeline.
//   M = S[50000,512] @ Wcat[512,64]; out = deg>0 ? relu(0.2f + 0.8/deg*M) : f
// Block = 128 rows x 64 cols, 256 threads (8 warps, one m16 tile each).
// Slice rs+1's A (128x64 S slice) and W tiles are cp.async'd into the other
// buffer while slice rs's mma runs; wait_group(1) + bar before consuming.
// ---------------------------------------------------------------------------
#define GT 256
#define A_STRIDE 68
#define W_STRIDE 72
#define A_BUF (128 * A_STRIDE)            // floats per A buffer (34816 B)
#define W_BUF (FDIM * W_STRIDE)           // u32 per W buffer (18432 B)
#define GEMM_SMEM ((2 * A_BUF + 2 * W_BUF) * 4)   // 106496 B

__device__ __forceinline__ void cp16(uint32_t smem_dst, const void* gsrc) {
    asm volatile("cp.async.ca.shared.global [%0], [%1], 16;"
                 :: "r"(smem_dst), "l"(gsrc));
}

__global__ __launch_bounds__(GT)
void k_gemm_final(const float* __restrict__ feat, float* __restrict__ out) {
    extern __shared__ float smraw[];
    float*    As = smraw;                        // [2][128][68]
    uint32_t* Ws = (uint32_t*)(smraw + 2 * A_BUF); // [2][64][72]
    const uint32_t as_u32 = (uint32_t)__cvta_generic_to_shared(As);
    const uint32_t ws_u32 = (uint32_t)__cvta_generic_to_shared(Ws);

    const float4* S4 = (const float4*)g_S;       // S row = 128 float4
    const int row0 = blockIdx.x * 128;
    const int tid  = threadIdx.x;
    const int warp = tid >> 5;
    const int lane = tid & 31;
    const int gid  = lane >> 2;    // 0..7
    const int kc   = lane & 3;     // 0..3
    const int wr   = warp * 16;

    // issue cp.asyncs for one relation slice into buffer `buf`
    auto issue = [&](int rs, int buf) {
        const float4* wsrc = (const float4*)(g_Wtf + (size_t)rs * W_BUF);
        uint32_t wdst = ws_u32 + buf * (W_BUF * 4);
        #pragma unroll
        for (int i = tid; i < W_BUF / 4; i += GT)        // 1152 float4
            cp16(wdst + i * 16, wsrc + i);
        uint32_t adst = as_u32 + buf * (A_BUF * 4);
        #pragma unroll
        for (int i = tid; i < 128 * 16; i += GT) {       // 2048 float4
            int rr = i >> 4, cc = i & 15;
            int n = row0 + rr;
            if (n >= N_NODES) n = N_NODES - 1;
            cp16(adst + (rr * A_STRIDE + cc * 4) * 4,
                 &S4[(size_t)n * (KDIM / 4) + rs * 16 + cc]);
        }
        asm volatile("cp.async.commit_group;");
    };

    float c[8][4];
    #pragma unroll
    for (int nt = 0; nt < 8; nt++)
        #pragma unroll
        for (int i = 0; i < 4; i++) c[nt][i] = 0.f;

    issue(0, 0);

    for (int rs = 0; rs < NRELS; rs++) {
        const int buf = rs & 1;
        __syncthreads();   // all warps done with mma(rs-1): buf[(rs+1)&1] reusable
        if (rs + 1 < NRELS) {
            issue(rs + 1, buf ^ 1);
            asm volatile("cp.async.wait_group 1;");  // slice rs landed
        } else {
            asm volatile("cp.async.wait_group 0;");
        }
        __syncthreads();   // cp.async data visible to all warps

        const float*    A = As + buf * A_BUF;
        const uint32_t* B = Ws + buf * W_BUF;
        #pragma unroll
        for (int ks = 0; ks < 8; ks++) {
            const int k0 = ks * 8;
            uint32_t a0 = f2tf32(A[(wr + gid) * A_STRIDE + k0 + kc]);
            uint32_t a1 = f2tf32(A[(wr + gid + 8) * A_STRIDE + k0 + kc]);
            uint32_t a2 = f2tf32(A[(wr + gid) * A_STRIDE + k0 + kc + 4]);
            uint32_t a3 = f2tf32(A[(wr + gid + 8) * A_STRIDE + k0 + kc + 4]);
            #pragma unroll
            for (int nt = 0; nt < 8; nt++) {
                uint32_t b0 = B[(k0 + kc) * W_STRIDE + nt * 8 + gid];
                uint32_t b1 = B[(k0 + kc + 4) * W_STRIDE + nt * 8 + gid];
                asm volatile(
                    "mma.sync.aligned.m16n8k8.row.col.f32.tf32.tf32.f32 "
                    "{%0,%1,%2,%3}, {%4,%5,%6,%7}, {%8,%9}, {%0,%1,%2,%3};"
                    : "+f"(c[nt][0]), "+f"(c[nt][1]), "+f"(c[nt][2]), "+f"(c[nt][3])
                    : "r"(a0), "r"(a1), "r"(a2), "r"(a3), "r"(b0), "r"(b1));
            }
        }
    }

    // fused epilogue: out = deg>0 ? relu(0.2*feat + (0.8/deg)*M) : feat
    {
        int r0 = row0 + wr + gid;
        int r1 = r0 + 8;
        bool v0 = r0 < N_NODES, v1 = r1 < N_NODES;
        int dg0 = v0 ? g_deg[r0] : 0;
        int dg1 = v1 ? g_deg[r1] : 0;
        float inv0 = dg0 > 0 ? 0.8f / (float)dg0 : 0.f;
        float inv1 = dg1 > 0 ? 0.8f / (float)dg1 : 0.f;
        #pragma unroll
        for (int nt = 0; nt < 8; nt++) {
            int col = nt * 8 + 2 * kc;
            if (v0) {
                float2 f = *(const float2*)&feat[(size_t)r0 * FDIM + col];
                float2 o;
                if (dg0 > 0) {
                    o.x = fmaxf(fmaf(c[nt][0], inv0, 0.2f * f.x), 0.f);
                    o.y = fmaxf(fmaf(c[nt][1], inv0, 0.2f * f.y), 0.f);
                } else o = f;
                *(float2*)&out[(size_t)r0 * FDIM + col] = o;
            }
            if (v1) {
                float2 f = *(const float2*)&feat[(size_t)r1 * FDIM + col];
                float2 o;
                if (dg1 > 0) {
                    o.x = fmaxf(fmaf(c[nt][2], inv1, 0.2f * f.x), 0.f);
                    o.y = fmaxf(fmaf(c[nt][3], inv1, 0.2f * f.y), 0.f);
                } else o = f;
                *(float2*)&out[(size_t)r1 * FDIM + col] = o;
            }
        }
    }
}

// ---------------------------------------------------------------------------
extern "C" void kernel_launch(void* const* d_in, const int* in_sizes, int n_in,
                              void* d_out, int out_size) {
    const float* feat = (const float*)d_in[0];   // [50000, 64] f32
    const float* W    = (const float*)d_in[1];   // [8, 64, 64] f32
    const int*   src  = (const int*)d_in[2];     // [800000] i32
    const int*   dst  = (const int*)d_in[3];     // [800000] i32
    const int*   et   = (const int*)d_in[4];     // [800000] i32
    float* out = (float*)d_out;                  // [50000, 64] f32

    static bool attr_set = false;
    if (!attr_set) {
        cudaFuncSetAttribute(k_gemm_final,
                             cudaFuncAttributeMaxDynamicSharedMemorySize, GEMM_SMEM);
        attr_set = true;
    }

    const size_t ZN = (size_t)N_NODES * (KDIM / 4);          // 6.4M float4
    k_zero<<<(int)((ZN + 255) / 256), 256>>>();
    k_cvtW<<<(NRELS * FDIM * FDIM + 255) / 256, 256>>>(W);
    k_pack_deg<<<(N_EDGES + 255) / 256, 256>>>(src, dst, et);
    k_scatter<<<(N_EDGES * 16 + 255) / 256, 256>>>((const float4*)feat);
    k_gemm_final<<<(N_NODES + 127) / 128, GT, GEMM_SMEM>>>(feat, out);
}

// round 16
// speedup vs baseline: 1.0341x; 1.0341x over previous
#include <cuda_runtime.h>
#include <cstdint>

#define N_NODES 50000
#define N_EDGES 800000
#define FDIM    64
#define NRELS   8
#define KDIM    (NRELS * FDIM)   // 512

// ---- scratch (allocation-free rule: __device__ globals) ----
// S[n, r, d] node-major accumulator = [50000, 512] fp32 (102.4 MB).
__device__ __align__(16) float g_S[(size_t)N_NODES * KDIM];
__device__ __align__(16) int2  g_epack[N_EDGES];   // {src, dst*8+etype}
__device__ int g_deg[N_NODES];

// ---------------------------------------------------------------------------
// K0: zero the scatter accumulator S and the degree array. (DRAM-BW bound,
// ~13us for 102.4 MB — already at peak.)
// ---------------------------------------------------------------------------
__global__ void k_zero() {
    size_t i = (size_t)blockIdx.x * blockDim.x + threadIdx.x;
    if (i < (size_t)N_NODES * (KDIM / 4))
        ((float4*)g_S)[i] = make_float4(0.f, 0.f, 0.f, 0.f);
    if (i < N_NODES) g_deg[i] = 0;
}

// ---------------------------------------------------------------------------
// K1: fused degree histogram + edge-index packing.
// ---------------------------------------------------------------------------
__global__ void k_pack_deg(const int* __restrict__ src, const int* __restrict__ dst,
                           const int* __restrict__ et) {
    int e = blockIdx.x * blockDim.x + threadIdx.x;
    if (e >= N_EDGES) return;
    int d = dst[e];
    g_epack[e] = make_int2(src[e], d * NRELS + et[e]);
    atomicAdd(&g_deg[d], 1);
}

// ---------------------------------------------------------------------------
// K2: edge scatter of RAW features. 16 lanes per edge, one float4 each.
// Measured at its REDG/LTS structural floor (~51us, occ 79%).
// ---------------------------------------------------------------------------
__global__ void k_scatter(const float4* __restrict__ feat4) {
    int t = blockIdx.x * blockDim.x + threadIdx.x;
    int e = t >> 4;
    int l = t & 15;
    if (e >= N_EDGES) return;
    int2 idx = __ldg(&g_epack[e]);
    float4 v = __ldg(&feat4[(size_t)idx.x * (FDIM / 4) + l]);
    float* o = g_S + (size_t)idx.y * FDIM + l * 4;
    asm volatile("red.global.add.v4.f32 [%0], {%1,%2,%3,%4};"
                 :: "l"(o), "f"(v.x), "f"(v.y), "f"(v.z), "f"(v.w) : "memory");
}

// ---------------------------------------------------------------------------
// K3: fused GEMM + epilogue, HIGH-OCCUPANCY direct-load version.
//   M = S[50000,512] @ Wcat[512,64]; out = deg>0 ? relu(0.2f + 0.8/deg*M) : f
// Block = 64 rows x 64 cols, 128 threads (4 warps, one m16 tile each)
// -> 782 blocks (5.3/SM). A-fragments loaded straight from (dirty-L2) g_S:
// 32 independent scalar LDGs per thread per slice, front-batched for MLP.
// Only W lives in smem (cross-warp reuse; stride 72 -> conflict-free LDS).
// ---------------------------------------------------------------------------
#define GT 128
#define W_STRIDE 72

__device__ __forceinline__ uint32_t f2tf32(float x) {
    uint32_t u;
    asm("cvt.rna.tf32.f32 %0, %1;" : "=r"(u) : "f"(x));
    return u;
}

__global__ __launch_bounds__(GT)
void k_gemm_final(const float* __restrict__ feat, const float* __restrict__ W,
                  float* __restrict__ out) {
    __shared__ uint32_t Ws[FDIM * W_STRIDE];   // 18432 B

    const int row0 = blockIdx.x * 64;
    const int tid  = threadIdx.x;
    const int warp = tid >> 5;     // 0..3
    const int lane = tid & 31;
    const int gid  = lane >> 2;    // 0..7
    const int kc   = lane & 3;     // 0..3
    const int wr   = warp * 16;

    // clamped fragment rows (loads in-bounds; stores predicated)
    int r0 = row0 + wr + gid;
    int r1 = r0 + 8;
    const int fr0 = r0 < N_NODES ? r0 : N_NODES - 1;
    const int fr1 = r1 < N_NODES ? r1 : N_NODES - 1;

    float c[8][4];
    #pragma unroll
    for (int nt = 0; nt < 8; nt++)
        #pragma unroll
        for (int i = 0; i < 4; i++) c[nt][i] = 0.f;

    for (int rs = 0; rs < NRELS; rs++) {
        __syncthreads();   // protect Ws from previous slice's readers

        // stage W_rs pre-rounded to tf32 (32 elems/thread, L2-hot source)
        const float* Wg = W + (size_t)rs * FDIM * FDIM;
        #pragma unroll
        for (int i = tid; i < FDIM * FDIM; i += GT)
            Ws[(i >> 6) * W_STRIDE + (i & 63)] = f2tf32(Wg[i]);

        // front-batch ALL A loads for this slice: 2 rows x 16 stride-4 scalars
        // (k = kc + 4t). 32 independent LDGs -> deep MLP; dirty-L2 hits.
        const float* p0 = g_S + (size_t)fr0 * KDIM + rs * FDIM + kc;
        const float* p1 = g_S + (size_t)fr1 * KDIM + rs * FDIM + kc;
        float A0[16], A1[16];
        #pragma unroll
        for (int t = 0; t < 16; t++) A0[t] = __ldg(p0 + 4 * t);
        #pragma unroll
        for (int t = 0; t < 16; t++) A1[t] = __ldg(p1 + 4 * t);

        __syncthreads();   // Ws staged

        #pragma unroll
        for (int ks = 0; ks < 8; ks++) {
            const int k0 = ks * 8;
            uint32_t a0 = f2tf32(A0[2 * ks]);
            uint32_t a1 = f2tf32(A1[2 * ks]);
            uint32_t a2 = f2tf32(A0[2 * ks + 1]);
            uint32_t a3 = f2tf32(A1[2 * ks + 1]);
            #pragma unroll
            for (int nt = 0; nt < 8; nt++) {
                uint32_t b0 = Ws[(k0 + kc) * W_STRIDE + nt * 8 + gid];
                uint32_t b1 = Ws[(k0 + kc + 4) * W_STRIDE + nt * 8 + gid];
                asm volatile(
                    "mma.sync.aligned.m16n8k8.row.col.f32.tf32.tf32.f32 "
                    "{%0,%1,%2,%3}, {%4,%5,%6,%7}, {%8,%9}, {%0,%1,%2,%3};"
                    : "+f"(c[nt][0]), "+f"(c[nt][1]), "+f"(c[nt][2]), "+f"(c[nt][3])
                    : "r"(a0), "r"(a1), "r"(a2), "r"(a3), "r"(b0), "r"(b1));
            }
        }
    }

    // fused epilogue: out = deg>0 ? relu(0.2*feat + (0.8/deg)*M) : feat
    {
        bool v0 = r0 < N_NODES, v1 = r1 < N_NODES;
        int dg0 = v0 ? g_deg[r0] : 0;
        int dg1 = v1 ? g_deg[r1] : 0;
        float inv0 = dg0 > 0 ? 0.8f / (float)dg0 : 0.f;
        float inv1 = dg1 > 0 ? 0.8f / (float)dg1 : 0.f;
        #pragma unroll
        for (int nt = 0; nt < 8; nt++) {
            int col = nt * 8 + 2 * kc;
            if (v0) {
                float2 f = *(const float2*)&feat[(size_t)r0 * FDIM + col];
                float2 o;
                if (dg0 > 0) {
                    o.x = fmaxf(fmaf(c[nt][0], inv0, 0.2f * f.x), 0.f);
                    o.y = fmaxf(fmaf(c[nt][1], inv0, 0.2f * f.y), 0.f);
                } else o = f;
                *(float2*)&out[(size_t)r0 * FDIM + col] = o;
            }
            if (v1) {
                float2 f = *(const float2*)&feat[(size_t)r1 * FDIM + col];
                float2 o;
                if (dg1 > 0) {
                    o.x = fmaxf(fmaf(c[nt][2], inv1, 0.2f * f.x), 0.f);
                    o.y = fmaxf(fmaf(c[nt][3], inv1, 0.2f * f.y), 0.f);
                } else o = f;
                *(float2*)&out[(size_t)r1 * FDIM + col] = o;
            }
        }
    }
}

// ---------------------------------------------------------------------------
extern "C" void kernel_launch(void* const* d_in, const int* in_sizes, int n_in,
                              void* d_out, int out_size) {
    const float* feat = (const float*)d_in[0];   // [50000, 64] f32
    const float* W    = (const float*)d_in[1];   // [8, 64, 64] f32
    const int*   src  = (const int*)d_in[2];     // [800000] i32
    const int*   dst  = (const int*)d_in[3];     // [800000] i32
    const int*   et   = (const int*)d_in[4];     // [800000] i32
    float* out = (float*)d_out;                  // [50000, 64] f32

    const size_t ZN = (size_t)N_NODES * (KDIM / 4);          // 6.4M float4
    k_zero<<<(int)((ZN + 255) / 256), 256>>>();
    k_pack_deg<<<(N_EDGES + 255) / 256, 256>>>(src, dst, et);
    k_scatter<<<(N_EDGES * 16 + 255) / 256, 256>>>((const float4*)feat);
    k_gemm_final<<<(N_NODES + 63) / 64, GT>>>(feat, W, out);
}

// round 17
// speedup vs baseline: 1.6664x; 1.6115x over previous
#include <cuda_runtime.h>
#include <cuda_fp16.h>
#include <cstdint>

#define N_NODES 50000
#define N_EDGES 800000
#define FDIM    64
#define NRELS   8
#define KDIM    (NRELS * FDIM)   // 512

// ---- scratch (allocation-free rule: __device__ globals) ----
// S16[n, r, d]: f16 message accumulator [50000, 512] (51.2 MB).
__device__ __align__(16) __half g_S16[(size_t)N_NODES * KDIM];
__device__ __align__(16) __half g_feat16[(size_t)N_NODES * FDIM];  // 6.4 MB
// W packed as half2 k-pairs: [8][32 kpairs][72 pad] u32 (73.7 KB).
#define WP_STRIDE 72
#define WP_SLICE  (32 * WP_STRIDE)      // 2304 u32 per relation
__device__ __align__(16) uint32_t g_Wp[NRELS * WP_SLICE];
__device__ __align__(16) int2 g_epack[N_EDGES];   // {src, dst*8+etype}
__device__ int g_deg[N_NODES];

// ---------------------------------------------------------------------------
// K0: zero S16 + deg.  51.2 MB -> ~7us DRAM-bound.
// ---------------------------------------------------------------------------
__global__ void k_zero() {
    size_t i = (size_t)blockIdx.x * blockDim.x + threadIdx.x;
    if (i < (size_t)N_NODES * KDIM / 8)
        ((uint4*)g_S16)[i] = make_uint4(0u, 0u, 0u, 0u);
    if (i < N_NODES) g_deg[i] = 0;
}

// ---------------------------------------------------------------------------
// K0b: convert feat to f16 (rounds once; scatter sums the rounded values).
// ---------------------------------------------------------------------------
__global__ void k_cvt_feat(const float2* __restrict__ feat2) {
    int i = blockIdx.x * blockDim.x + threadIdx.x;   // over N*32 float2
    if (i >= N_NODES * (FDIM / 2)) return;
    float2 v = __ldg(&feat2[i]);
    ((__half2*)g_feat16)[i] = __floats2half2_rn(v.x, v.y);
}

// ---------------------------------------------------------------------------
// K0c: pack W into half2 k-pairs: g_Wp[r][kp][col] = (W[r][2kp][col], W[r][2kp+1][col]).
// ---------------------------------------------------------------------------
__global__ void k_cvtW(const float* __restrict__ W) {
    int i = blockIdx.x * blockDim.x + threadIdx.x;   // over 8*32*64
    if (i >= NRELS * 32 * FDIM) return;
    int r = i >> 11, kp = (i >> 6) & 31, col = i & 63;
    const float* base = W + (size_t)r * FDIM * FDIM + 2 * kp * FDIM + col;
    __half2 h = __floats2half2_rn(base[0], base[FDIM]);
    g_Wp[r * WP_SLICE + kp * WP_STRIDE + col] = *(uint32_t*)&h;
}

// ---------------------------------------------------------------------------
// K1: fused degree histogram + edge-index packing.
// ---------------------------------------------------------------------------
__global__ void k_pack_deg(const int* __restrict__ src, const int* __restrict__ dst,
                           const int* __restrict__ et) {
    int e = blockIdx.x * blockDim.x + threadIdx.x;
    if (e >= N_EDGES) return;
    int d = dst[e];
    g_epack[e] = make_int2(src[e], d * NRELS + et[e]);
    atomicAdd(&g_deg[d], 1);
}

// ---------------------------------------------------------------------------
// K2: edge scatter, f16 payload. 8 lanes per edge: LDG.128 (8 halves from
// the 6.4 MB L1-hot feat16) + one red.v4.f16x2 (16B). Half the RED lane-ops
// of the fp32 version -> new REDG floor ~28us.
// ---------------------------------------------------------------------------
__global__ void k_scatter() {
    int t = blockIdx.x * blockDim.x + threadIdx.x;
    int e = t >> 3;
    int l = t & 7;
    if (e >= N_EDGES) return;
    int2 idx = __ldg(&g_epack[e]);
    uint4 v = __ldg((const uint4*)(g_feat16 + (size_t)idx.x * FDIM) + l);
    __half* o = g_S16 + (size_t)idx.y * FDIM + l * 8;
    asm volatile("red.global.add.noftz.v4.f16x2 [%0], {%1,%2,%3,%4};"
                 :: "l"(o), "r"(v.x), "r"(v.y), "r"(v.z), "r"(v.w) : "memory");
}

// ---------------------------------------------------------------------------
// K3: fused GEMM + epilogue, f16 mma.m16n8k16, ALL W resident in smem.
//   M = S16[50000,512] @ Wcat[512,64]; out = deg>0 ? relu(0.2f+0.8/deg*M) : f
// Block = 128 rows x 64 cols, 256 threads (8 warps x one m16 tile).
// Stage all 8 W slices (73.7 KB) once -> main loop has NO barriers: per
// relation slice, 16 front-batched f16x2 A loads + 32 mma. B smem reads:
// bank = kc*8+gid (stride 72) -> conflict-free.
// ---------------------------------------------------------------------------
#define GT 256
#define GEMM_SMEM (NRELS * WP_SLICE * 4)   // 73728 B

__global__ __launch_bounds__(GT, 3)
void k_gemm_final(const float* __restrict__ feat, float* __restrict__ out) {
    extern __shared__ uint32_t Wsm[];   // [8][32][72]

    const int row0 = blockIdx.x * 128;
    const int tid  = threadIdx.x;
    const int warp = tid >> 5;     // 0..7
    const int lane = tid & 31;
    const int gid  = lane >> 2;    // 0..7  (row in group / B col)
    const int kc   = lane & 3;     // 0..3
    const int wr   = warp * 16;

    // stage all of W once: 4608 uint4, 18 per thread, coalesced
    #pragma unroll
    for (int i = tid; i < NRELS * WP_SLICE / 4; i += GT)
        ((uint4*)Wsm)[i] = ((const uint4*)g_Wp)[i];

    int r0 = row0 + wr + gid;
    int r1 = r0 + 8;
    const int fr0 = r0 < N_NODES ? r0 : N_NODES - 1;
    const int fr1 = r1 < N_NODES ? r1 : N_NODES - 1;

    float c[8][4];
    #pragma unroll
    for (int nt = 0; nt < 8; nt++)
        #pragma unroll
        for (int i = 0; i < 4; i++) c[nt][i] = 0.f;

    __syncthreads();   // W staged; no further barriers

    #pragma unroll
    for (int rs = 0; rs < NRELS; rs++) {
        // front-batch all 16 A-fragment loads for this slice (f16x2 each)
        const __half* b0 = g_S16 + (size_t)fr0 * KDIM + rs * FDIM + 2 * kc;
        const __half* b1 = g_S16 + (size_t)fr1 * KDIM + rs * FDIM + 2 * kc;
        uint32_t A0[8], A1[8];
        #pragma unroll
        for (int ks = 0; ks < 4; ks++) {
            A0[2 * ks]     = *(const uint32_t*)(b0 + 16 * ks);
            A0[2 * ks + 1] = *(const uint32_t*)(b0 + 16 * ks + 8);
            A1[2 * ks]     = *(const uint32_t*)(b1 + 16 * ks);
            A1[2 * ks + 1] = *(const uint32_t*)(b1 + 16 * ks + 8);
        }
        const uint32_t* Wr = Wsm + rs * WP_SLICE;
        #pragma unroll
        for (int ks = 0; ks < 4; ks++) {
            #pragma unroll
            for (int nt = 0; nt < 8; nt++) {
                uint32_t wb0 = Wr[(8 * ks + kc) * WP_STRIDE + nt * 8 + gid];
                uint32_t wb1 = Wr[(8 * ks + kc + 4) * WP_STRIDE + nt * 8 + gid];
                asm volatile(
                    "mma.sync.aligned.m16n8k16.row.col.f32.f16.f16.f32 "
                    "{%0,%1,%2,%3}, {%4,%5,%6,%7}, {%8,%9}, {%0,%1,%2,%3};"
                    : "+f"(c[nt][0]), "+f"(c[nt][1]), "+f"(c[nt][2]), "+f"(c[nt][3])
                    : "r"(A0[2 * ks]), "r"(A1[2 * ks]),
                      "r"(A0[2 * ks + 1]), "r"(A1[2 * ks + 1]),
                      "r"(wb0), "r"(wb1));
            }
        }
    }

    // fused epilogue: out = deg>0 ? relu(0.2*feat + (0.8/deg)*M) : feat
    {
        bool v0 = r0 < N_NODES, v1 = r1 < N_NODES;
        int dg0 = v0 ? g_deg[r0] : 0;
        int dg1 = v1 ? g_deg[r1] : 0;
        float inv0 = dg0 > 0 ? 0.8f / (float)dg0 : 0.f;
        float inv1 = dg1 > 0 ? 0.8f / (float)dg1 : 0.f;
        #pragma unroll
        for (int nt = 0; nt < 8; nt++) {
            int col = nt * 8 + 2 * kc;
            if (v0) {
                float2 f = *(const float2*)&feat[(size_t)r0 * FDIM + col];
                float2 o;
                if (dg0 > 0) {
                    o.x = fmaxf(fmaf(c[nt][0], inv0, 0.2f * f.x), 0.f);
                    o.y = fmaxf(fmaf(c[nt][1], inv0, 0.2f * f.y), 0.f);
                } else o = f;
                *(float2*)&out[(size_t)r0 * FDIM + col] = o;
            }
            if (v1) {
                float2 f = *(const float2*)&feat[(size_t)r1 * FDIM + col];
                float2 o;
                if (dg1 > 0) {
                    o.x = fmaxf(fmaf(c[nt][2], inv1, 0.2f * f.x), 0.f);
                    o.y = fmaxf(fmaf(c[nt][3], inv1, 0.2f * f.y), 0.f);
                } else o = f;
                *(float2*)&out[(size_t)r1 * FDIM + col] = o;
            }
        }
    }
}

// ---------------------------------------------------------------------------
extern "C" void kernel_launch(void* const* d_in, const int* in_sizes, int n_in,
                              void* d_out, int out_size) {
    const float* feat = (const float*)d_in[0];   // [50000, 64] f32
    const float* W    = (const float*)d_in[1];   // [8, 64, 64] f32
    const int*   src  = (const int*)d_in[2];     // [800000] i32
    const int*   dst  = (const int*)d_in[3];     // [800000] i32
    const int*   et   = (const int*)d_in[4];     // [800000] i32
    float* out = (float*)d_out;                  // [50000, 64] f32

    static bool attr_set = false;
    if (!attr_set) {
        cudaFuncSetAttribute(k_gemm_final,
                             cudaFuncAttributeMaxDynamicSharedMemorySize, GEMM_SMEM);
        attr_set = true;
    }

    const size_t ZN = (size_t)N_NODES * KDIM / 8;            // 3.2M uint4
    k_zero<<<(int)((ZN + 255) / 256), 256>>>();
    k_cvt_feat<<<(N_NODES * (FDIM / 2) + 255) / 256, 256>>>((const float2*)feat);
    k_cvtW<<<(NRELS * 32 * FDIM + 255) / 256, 256>>>(W);
    k_pack_deg<<<(N_EDGES + 255) / 256, 256>>>(src, dst, et);
    k_scatter<<<(N_EDGES * 8 + 255) / 256, 256>>>();
    k_gemm_final<<<(N_NODES + 127) / 128, GT, GEMM_SMEM>>>(feat, out);
}